// round 1
// baseline (speedup 1.0000x reference)
#include <cuda_runtime.h>
#include <math.h>

#define BB    64
#define TT    256
#define WW    20
#define NP    6
#define NT    12
#define CH    32
#define LL1   18
#define LL2   16
#define PROJD 64
#define GATES 256
#define NWIN  (BB*TT)   // 16384

// Scratch (device globals per allocation rules)
__device__ float g_xg[NWIN * GATES];   // 16 MB: precomputed input gates
__device__ float g_hs[NWIN * PROJD];   // 4 MB : all LSTM hidden states

// ---------------------------------------------------------------------------
// Encoder: one warp = one window. lane = output channel (0..31).
// conv1 (valid, K=3) -> relu -> conv2 -> relu -> mean. Weights in registers,
// activations staged through per-warp smem (broadcast LDS reads).
// ---------------------------------------------------------------------------
template<int CIN>
__device__ __forceinline__ void encode_win(
    const float* __restrict__ xs,          // smem [CIN][WW]
    const float* __restrict__ w1, const float* __restrict__ b1,
    const float* __restrict__ w2, const float* __restrict__ b2,
    float* __restrict__ h1s,               // smem [CH][LL1]
    float* __restrict__ outp, int lane)
{
    const int oc = lane;
    // conv1
    float acc[LL1];
    float bb = __ldg(b1 + oc);
    #pragma unroll
    for (int p = 0; p < LL1; p++) acc[p] = bb;
    for (int ic = 0; ic < CIN; ic++) {
        float xv[WW];
        #pragma unroll
        for (int l = 0; l < WW; l++) xv[l] = xs[ic * WW + l];
        const float* wr = w1 + (oc * CIN + ic) * 3;
        float w0 = __ldg(wr), w1v = __ldg(wr + 1), w2v = __ldg(wr + 2);
        #pragma unroll
        for (int p = 0; p < LL1; p++)
            acc[p] += xv[p] * w0 + xv[p + 1] * w1v + xv[p + 2] * w2v;
    }
    #pragma unroll
    for (int p = 0; p < LL1; p++) h1s[oc * LL1 + p] = fmaxf(acc[p], 0.f);
    __syncwarp();
    // conv2 + relu + mean (no need to materialize h2)
    float s[LL2];
    float bb2 = __ldg(b2 + oc);
    #pragma unroll
    for (int p = 0; p < LL2; p++) s[p] = bb2;
    for (int ic = 0; ic < CH; ic++) {
        float hv[LL1];
        #pragma unroll
        for (int p = 0; p < LL1; p++) hv[p] = h1s[ic * LL1 + p];
        const float* wr = w2 + (oc * CH + ic) * 3;
        float w0 = __ldg(wr), w1v = __ldg(wr + 1), w2v = __ldg(wr + 2);
        #pragma unroll
        for (int p = 0; p < LL2; p++)
            s[p] += hv[p] * w0 + hv[p + 1] * w1v + hv[p + 2] * w2v;
    }
    float sum = 0.f;
    #pragma unroll
    for (int p = 0; p < LL2; p++) sum += fmaxf(s[p], 0.f);
    outp[oc] = sum * (1.f / 16.f);
    __syncwarp();   // protect h1s before reuse by the next encoder
}

__global__ __launch_bounds__(128) void encode_kernel(
    const float* __restrict__ pressure, const float* __restrict__ torque,
    const float* __restrict__ frag,
    const float* __restrict__ pw1, const float* __restrict__ pb1,
    const float* __restrict__ pw2, const float* __restrict__ pb2,
    const float* __restrict__ tw1, const float* __restrict__ tb1,
    const float* __restrict__ tw2, const float* __restrict__ tb2,
    const float* __restrict__ fw,  const float* __restrict__ fb,
    const float* __restrict__ prw, const float* __restrict__ prb,
    const float* __restrict__ Wih, const float* __restrict__ bih,
    const float* __restrict__ bhh)
{
    __shared__ __align__(16) float s_x[4][NT * WW];      // 240 floats/warp
    __shared__ __align__(16) float s_h1[4][CH * LL1];    // 576 floats/warp
    __shared__ __align__(16) float s_cat[4][80];         // 72 used, padded
    __shared__ __align__(16) float s_feat[4][PROJD];

    const int warp = threadIdx.x >> 5, lane = threadIdx.x & 31;
    const int n = blockIdx.x * 4 + warp;       // window index in [0, 16384)
    const int b = n / TT;

    float* xs   = s_x[warp];
    float* h1s  = s_h1[warp];
    float* cats = s_cat[warp];
    float* feats = s_feat[warp];

    // pressure window: (W, NP) in gmem -> xs[c][l]
    for (int i = lane; i < WW * NP; i += 32) {
        int l = i / NP, c = i % NP;
        xs[c * WW + l] = __ldg(pressure + (size_t)n * (WW * NP) + i);
    }
    __syncwarp();
    encode_win<NP>(xs, pw1, pb1, pw2, pb2, h1s, cats, lane);

    // torque window
    for (int i = lane; i < WW * NT; i += 32) {
        int l = i / NT, c = i % NT;
        xs[c * WW + l] = __ldg(torque + (size_t)n * (WW * NT) + i);
    }
    __syncwarp();
    encode_win<NT>(xs, tw1, tb1, tw2, tb2, h1s, cats + CH, lane);

    // fragility features (8)
    if (lane < 8) {
        float fv = __ldg(frag + b);
        cats[2 * CH + lane] = fmaxf(fv * __ldg(fw + lane) + __ldg(fb + lane), 0.f);
    }
    __syncwarp();

    // projection: 72 -> 64, relu. 2 outputs per lane.
    #pragma unroll
    for (int r = 0; r < 2; r++) {
        int j = lane + 32 * r;
        float a = __ldg(prb + j);
        const float4* wr = (const float4*)(prw + j * 72);   // 288B rows, 16B aligned
        #pragma unroll
        for (int k = 0; k < 18; k++) {
            float4 w = __ldg(wr + k);
            float4 cv = *(const float4*)(cats + 4 * k);
            a += cv.x * w.x + cv.y * w.y + cv.z * w.z + cv.w * w.w;
        }
        feats[j] = fmaxf(a, 0.f);
    }
    __syncwarp();

    // xg = feat @ Wih^T + (bih + bhh): 256 outputs, 8 per lane.
    float* xgo = g_xg + (size_t)n * GATES;
    #pragma unroll
    for (int u = 0; u < 8; u++) {
        int g = lane + 32 * u;
        float a = __ldg(bih + g) + __ldg(bhh + g);
        const float4* wr = (const float4*)(Wih + g * PROJD);
        #pragma unroll
        for (int k = 0; k < 16; k++) {
            float4 w = __ldg(wr + k);
            float4 fv = *(const float4*)(feats + 4 * k);
            a += fv.x * w.x + fv.y * w.y + fv.z * w.z + fv.w * w.w;
        }
        xgo[g] = a;
    }
}

// ---------------------------------------------------------------------------
// LSTM: one block per batch row, thread = gate (0..255). Whh row in registers,
// h in smem. Writes all h states to g_hs; final (hT, cT) into d_out tail.
// ---------------------------------------------------------------------------
__device__ __forceinline__ float sigf(float x) { return 1.f / (1.f + __expf(-x)); }

__global__ __launch_bounds__(256) void lstm_kernel(
    const float* __restrict__ Whh, float* __restrict__ out_tail)
{
    const int b = blockIdx.x;
    const int g = threadIdx.x;

    __shared__ __align__(16) float h_s[PROJD];
    __shared__ float g_sh[GATES];

    float whh[PROJD];
    const float4* wr = (const float4*)(Whh + g * PROJD);
    #pragma unroll
    for (int k = 0; k < 16; k++) {
        float4 w = __ldg(wr + k);
        whh[4 * k] = w.x; whh[4 * k + 1] = w.y; whh[4 * k + 2] = w.z; whh[4 * k + 3] = w.w;
    }
    if (g < PROJD) h_s[g] = 0.f;
    float c = 0.f;
    __syncthreads();

    const float* xgb = g_xg + (size_t)b * TT * GATES + g;
    float xnext = xgb[0];
    float* hso = g_hs + (size_t)b * TT * PROJD;

    for (int t = 0; t < TT; t++) {
        float gv = xnext;
        if (t + 1 < TT) xnext = xgb[(t + 1) * GATES];   // prefetch next step
        #pragma unroll
        for (int k = 0; k < PROJD; k += 4) {
            float4 hv = *(const float4*)(h_s + k);
            gv += hv.x * whh[k] + hv.y * whh[k + 1] + hv.z * whh[k + 2] + hv.w * whh[k + 3];
        }
        g_sh[g] = gv;
        __syncthreads();
        if (g < PROJD) {
            float iv = g_sh[g], fv = g_sh[g + 64], gg = g_sh[g + 128], ov = g_sh[g + 192];
            c = sigf(fv) * c + sigf(iv) * tanhf(gg);
            float hn = sigf(ov) * tanhf(c);
            h_s[g] = hn;
            hso[t * PROJD + g] = hn;
        }
        __syncthreads();
    }
    if (g < PROJD) {
        out_tail[NWIN * 4 + b * PROJD + g] = h_s[g];                 // hT
        out_tail[NWIN * 4 + BB * PROJD + b * PROJD + g] = c;         // cT
    }
}

// ---------------------------------------------------------------------------
// Head: out[b,t,k] = sigmoid(h . hw[k] + hb[k]); fully parallel.
// ---------------------------------------------------------------------------
__global__ __launch_bounds__(256) void head_kernel(
    const float* __restrict__ hw, const float* __restrict__ hb,
    float* __restrict__ out)
{
    int idx = blockIdx.x * blockDim.x + threadIdx.x;
    if (idx >= NWIN * 4) return;
    int k = idx & 3;
    int n = idx >> 2;
    const float4* hp = (const float4*)(g_hs + (size_t)n * PROJD);
    const float4* wp = (const float4*)(hw + k * PROJD);
    float a = __ldg(hb + k);
    #pragma unroll
    for (int q = 0; q < 16; q++) {
        float4 h = hp[q];
        float4 w = __ldg(wp + q);
        a += h.x * w.x + h.y * w.y + h.z * w.z + h.w * w.w;
    }
    out[idx] = 1.f / (1.f + expf(-a));
}

// ---------------------------------------------------------------------------
extern "C" void kernel_launch(void* const* d_in, const int* in_sizes, int n_in,
                              void* d_out, int out_size)
{
    const float* pressure = (const float*)d_in[0];
    const float* torque   = (const float*)d_in[1];
    const float* frag     = (const float*)d_in[2];
    const float* pw1 = (const float*)d_in[3];
    const float* pb1 = (const float*)d_in[4];
    const float* pw2 = (const float*)d_in[5];
    const float* pb2 = (const float*)d_in[6];
    const float* tw1 = (const float*)d_in[7];
    const float* tb1 = (const float*)d_in[8];
    const float* tw2 = (const float*)d_in[9];
    const float* tb2 = (const float*)d_in[10];
    const float* fw  = (const float*)d_in[11];
    const float* fb  = (const float*)d_in[12];
    const float* prw = (const float*)d_in[13];
    const float* prb = (const float*)d_in[14];
    const float* Wih = (const float*)d_in[15];
    const float* Whh = (const float*)d_in[16];
    const float* bih = (const float*)d_in[17];
    const float* bhh = (const float*)d_in[18];
    const float* hw  = (const float*)d_in[19];
    const float* hb  = (const float*)d_in[20];
    float* out = (float*)d_out;

    encode_kernel<<<NWIN / 4, 128>>>(pressure, torque, frag,
                                     pw1, pb1, pw2, pb2, tw1, tb1, tw2, tb2,
                                     fw, fb, prw, prb, Wih, bih, bhh);
    lstm_kernel<<<BB, 256>>>(Whh, out);
    head_kernel<<<(NWIN * 4 + 255) / 256, 256>>>(hw, hb, out);
}

// round 2
// speedup vs baseline: 2.3014x; 2.3014x over previous
#include <cuda_runtime.h>
#include <math.h>

#define BB    64
#define TT    256
#define WW    20
#define NP    6
#define NT    12
#define CH    32
#define LL1   18
#define LL2   16
#define PROJD 64
#define GATES 256
#define NWIN  (BB*TT)   // 16384

#define ENC_GRID    148
#define ENC_THREADS 512
#define ENC_WARPS   (ENC_THREADS/32)

// Scratch (device globals per allocation rules)
__device__ float g_xg[NWIN * GATES];   // 16 MB: precomputed input gates
__device__ float g_hs[NWIN * PROJD];   // 4 MB : all LSTM hidden states

// ---- shared memory layout (floats) -----------------------------------------
#define S_W1P   0                         // [6*3][32]   = 576
#define S_W2P   (S_W1P + 576)             // [32*3][32]  = 3072
#define S_W1T   (S_W2P + 3072)            // [12*3][32]  = 1152
#define S_W2T   (S_W1T + 1152)            // [32*3][32]  = 3072
#define S_PRWT  (S_W2T + 3072)            // [72][64]    = 4608
#define S_WIHT  (S_PRWT + 4608)           // [64][256]   = 16384
#define S_B1P   (S_WIHT + 16384)          // 32
#define S_B2P   (S_B1P + 32)              // 32
#define S_B1T   (S_B2P + 32)              // 32
#define S_B2T   (S_B1T + 32)              // 32
#define S_PRB   (S_B2T + 32)              // 64
#define S_BSUM  (S_PRB + 64)              // 256
#define S_FW    (S_BSUM + 256)            // 8
#define S_FB    (S_FW + 8)                // 8 (+ pad to 16B)
#define S_WARP  (S_FB + 24)               // per-warp region start (16B aligned)

// per-warp buffer layout (floats), stride padded
#define PW_XS    0                        // [12][20] = 240
#define PW_H1    240                      // [32][20] = 640
#define PW_CAT   880                      // 72 (pad 16B ok: 880*4=3520)
#define PW_FEAT  952                      // 64
#define PW_SIZE  1024
#define SMEM_FLOATS (S_WARP + ENC_WARPS * PW_SIZE)
#define SMEM_BYTES  (SMEM_FLOATS * 4)

// ---------------------------------------------------------------------------
// One encoder pass: warp processes one window, lane = output channel.
// Weights come from conflict-free smem; activations via broadcast LDS.
// ---------------------------------------------------------------------------
template<int CIN>
__device__ __forceinline__ void encode_smem(
    const float* __restrict__ xs,     // [CIN][20]
    const float* __restrict__ w1s,    // [CIN*3][32]
    const float* __restrict__ b1s,
    const float* __restrict__ w2s,    // [32*3][32]
    const float* __restrict__ b2s,
    float* __restrict__ h1s,          // [32][20]
    float* __restrict__ outp, int lane)
{
    // conv1 -> relu -> h1s
    float acc[LL1];
    {
        float bb = b1s[lane];
        #pragma unroll
        for (int p = 0; p < LL1; p++) acc[p] = bb;
    }
    #pragma unroll 1
    for (int ic = 0; ic < CIN; ic++) {
        float xv[WW];
        const float4* xp = (const float4*)(xs + ic * WW);
        #pragma unroll
        for (int q = 0; q < 5; q++) ((float4*)xv)[q] = xp[q];
        float w0 = w1s[(ic * 3 + 0) * 32 + lane];
        float w1v = w1s[(ic * 3 + 1) * 32 + lane];
        float w2v = w1s[(ic * 3 + 2) * 32 + lane];
        #pragma unroll
        for (int p = 0; p < LL1; p++)
            acc[p] += xv[p] * w0 + xv[p + 1] * w1v + xv[p + 2] * w2v;
    }
    #pragma unroll
    for (int p = 0; p < LL1; p++) h1s[lane * WW + p] = fmaxf(acc[p], 0.f);
    __syncwarp();

    // conv2 -> relu -> mean
    float s[LL2];
    {
        float bb = b2s[lane];
        #pragma unroll
        for (int p = 0; p < LL2; p++) s[p] = bb;
    }
    #pragma unroll 1
    for (int ic = 0; ic < CH; ic++) {
        float hv[LL1];
        const float4* hp = (const float4*)(h1s + ic * WW);
        #pragma unroll
        for (int q = 0; q < 4; q++) ((float4*)hv)[q] = hp[q];
        ((float2*)hv)[8] = ((const float2*)hp)[8];
        float w0 = w2s[(ic * 3 + 0) * 32 + lane];
        float w1v = w2s[(ic * 3 + 1) * 32 + lane];
        float w2v = w2s[(ic * 3 + 2) * 32 + lane];
        #pragma unroll
        for (int p = 0; p < LL2; p++)
            s[p] += hv[p] * w0 + hv[p + 1] * w1v + hv[p + 2] * w2v;
    }
    float sum = 0.f;
    #pragma unroll
    for (int p = 0; p < LL2; p++) sum += fmaxf(s[p], 0.f);
    outp[lane] = sum * (1.f / 16.f);
    __syncwarp();   // outp / h1s ready & safely reusable
}

// ---------------------------------------------------------------------------
__global__ __launch_bounds__(ENC_THREADS, 1) void encode_kernel(
    const float* __restrict__ pressure, const float* __restrict__ torque,
    const float* __restrict__ frag,
    const float* __restrict__ pw1, const float* __restrict__ pb1,
    const float* __restrict__ pw2, const float* __restrict__ pb2,
    const float* __restrict__ tw1, const float* __restrict__ tb1,
    const float* __restrict__ tw2, const float* __restrict__ tb2,
    const float* __restrict__ fw,  const float* __restrict__ fb,
    const float* __restrict__ prw, const float* __restrict__ prb,
    const float* __restrict__ Wih, const float* __restrict__ bih,
    const float* __restrict__ bhh)
{
    extern __shared__ __align__(16) float sm[];
    const int tid = threadIdx.x;
    const int warp = tid >> 5, lane = tid & 31;

    // ---- stage all weights into smem (transposed, conflict-free) ----
    for (int i = tid; i < 32 * NP * 3; i += ENC_THREADS)
        sm[S_W1P + i] = pw1[(i & 31) * (NP * 3) + (i >> 5)];
    for (int i = tid; i < 32 * CH * 3; i += ENC_THREADS)
        sm[S_W2P + i] = pw2[(i & 31) * (CH * 3) + (i >> 5)];
    for (int i = tid; i < 32 * NT * 3; i += ENC_THREADS)
        sm[S_W1T + i] = tw1[(i & 31) * (NT * 3) + (i >> 5)];
    for (int i = tid; i < 32 * CH * 3; i += ENC_THREADS)
        sm[S_W2T + i] = tw2[(i & 31) * (CH * 3) + (i >> 5)];
    for (int i = tid; i < 72 * 64; i += ENC_THREADS)
        sm[S_PRWT + i] = prw[(i & 63) * 72 + (i >> 6)];
    for (int i = tid; i < 64 * 256; i += ENC_THREADS)
        sm[S_WIHT + i] = Wih[(i & 255) * 64 + (i >> 8)];
    if (tid < 32) {
        sm[S_B1P + tid] = pb1[tid];
        sm[S_B2P + tid] = pb2[tid];
        sm[S_B1T + tid] = tb1[tid];
        sm[S_B2T + tid] = tb2[tid];
    }
    if (tid < 64) sm[S_PRB + tid] = prb[tid];
    if (tid < GATES) sm[S_BSUM + tid] = bih[tid] + bhh[tid];
    if (tid < 8) { sm[S_FW + tid] = fw[tid]; sm[S_FB + tid] = fb[tid]; }
    __syncthreads();

    float* wb = sm + S_WARP + warp * PW_SIZE;
    float* xs    = wb + PW_XS;
    float* h1s   = wb + PW_H1;
    float* cats  = wb + PW_CAT;
    float* feats = wb + PW_FEAT;

    const int gwarp = blockIdx.x * ENC_WARPS + warp;

    for (int n = gwarp; n < NWIN; n += ENC_GRID * ENC_WARPS) {
        const int b = n / TT;

        // pressure window (W, NP) -> xs[c][20]
        {
            const float* src = pressure + (size_t)n * (WW * NP);
            for (int i = lane; i < WW * NP; i += 32) {
                int l = i / NP, c = i % NP;
                xs[c * WW + l] = src[i];
            }
        }
        __syncwarp();
        encode_smem<NP>(xs, sm + S_W1P, sm + S_B1P, sm + S_W2P, sm + S_B2P,
                        h1s, cats, lane);

        // torque window
        {
            const float* src = torque + (size_t)n * (WW * NT);
            for (int i = lane; i < WW * NT; i += 32) {
                int l = i / NT, c = i % NT;
                xs[c * WW + l] = src[i];
            }
        }
        __syncwarp();
        encode_smem<NT>(xs, sm + S_W1T, sm + S_B1T, sm + S_W2T, sm + S_B2T,
                        h1s, cats + CH, lane);

        // fragility features
        if (lane < 8) {
            float fv = __ldg(frag + b);
            cats[2 * CH + lane] = fmaxf(fv * sm[S_FW + lane] + sm[S_FB + lane], 0.f);
        }
        __syncwarp();

        // projection 72 -> 64 (relu); 2 outputs per lane via transposed weights
        {
            float a0 = sm[S_PRB + lane];
            float a1 = sm[S_PRB + lane + 32];
            const float* pw = sm + S_PRWT;
            #pragma unroll 8
            for (int k = 0; k < 72; k++) {
                float cv = cats[k];
                a0 += cv * pw[k * 64 + lane];
                a1 += cv * pw[k * 64 + lane + 32];
            }
            feats[lane]      = fmaxf(a0, 0.f);
            feats[lane + 32] = fmaxf(a1, 0.f);
        }
        __syncwarp();

        // xg = feat @ Wih^T + (bih+bhh); 8 gates per lane via transposed Wih
        {
            float acc[8];
            #pragma unroll
            for (int u = 0; u < 8; u++) acc[u] = sm[S_BSUM + lane + 32 * u];
            const float* wt = sm + S_WIHT;
            #pragma unroll 4
            for (int k = 0; k < PROJD; k++) {
                float fv = feats[k];
                #pragma unroll
                for (int u = 0; u < 8; u++)
                    acc[u] += fv * wt[k * 256 + lane + 32 * u];
            }
            float* xgo = g_xg + (size_t)n * GATES;
            #pragma unroll
            for (int u = 0; u < 8; u++) xgo[lane + 32 * u] = acc[u];
        }
        __syncwarp();   // cats/feats reusable next iteration
    }
}

// ---------------------------------------------------------------------------
// LSTM: one block per batch row, thread = gate (0..255).
// ---------------------------------------------------------------------------
__device__ __forceinline__ float sigf(float x) { return 1.f / (1.f + __expf(-x)); }

__global__ __launch_bounds__(256) void lstm_kernel(
    const float* __restrict__ Whh, float* __restrict__ out_tail)
{
    const int b = blockIdx.x;
    const int g = threadIdx.x;

    __shared__ __align__(16) float h_s[PROJD];
    __shared__ float g_sh[GATES];

    float whh[PROJD];
    const float4* wr = (const float4*)(Whh + g * PROJD);
    #pragma unroll
    for (int k = 0; k < 16; k++) {
        float4 w = __ldg(wr + k);
        whh[4 * k] = w.x; whh[4 * k + 1] = w.y; whh[4 * k + 2] = w.z; whh[4 * k + 3] = w.w;
    }
    if (g < PROJD) h_s[g] = 0.f;
    float c = 0.f;
    __syncthreads();

    const float* xgb = g_xg + (size_t)b * TT * GATES + g;
    float xnext = xgb[0];
    float* hso = g_hs + (size_t)b * TT * PROJD;

    for (int t = 0; t < TT; t++) {
        float gv = xnext;
        if (t + 1 < TT) xnext = xgb[(t + 1) * GATES];   // prefetch next step
        #pragma unroll
        for (int k = 0; k < PROJD; k += 4) {
            float4 hv = *(const float4*)(h_s + k);
            gv += hv.x * whh[k] + hv.y * whh[k + 1] + hv.z * whh[k + 2] + hv.w * whh[k + 3];
        }
        g_sh[g] = gv;
        __syncthreads();
        if (g < PROJD) {
            float iv = g_sh[g], fv = g_sh[g + 64], gg = g_sh[g + 128], ov = g_sh[g + 192];
            c = sigf(fv) * c + sigf(iv) * tanhf(gg);
            float hn = sigf(ov) * tanhf(c);
            h_s[g] = hn;
            hso[t * PROJD + g] = hn;
        }
        __syncthreads();
    }
    if (g < PROJD) {
        out_tail[NWIN * 4 + b * PROJD + g] = h_s[g];                 // hT
        out_tail[NWIN * 4 + BB * PROJD + b * PROJD + g] = c;         // cT
    }
}

// ---------------------------------------------------------------------------
// Head: out[n,k] = sigmoid(h[n] . hw[k] + hb[k])
// ---------------------------------------------------------------------------
__global__ __launch_bounds__(256) void head_kernel(
    const float* __restrict__ hw, const float* __restrict__ hb,
    float* __restrict__ out)
{
    int idx = blockIdx.x * blockDim.x + threadIdx.x;
    if (idx >= NWIN * 4) return;
    int k = idx & 3;
    int n = idx >> 2;
    const float4* hp = (const float4*)(g_hs + (size_t)n * PROJD);
    const float4* wp = (const float4*)(hw + k * PROJD);
    float a = __ldg(hb + k);
    #pragma unroll
    for (int q = 0; q < 16; q++) {
        float4 h = hp[q];
        float4 w = __ldg(wp + q);
        a += h.x * w.x + h.y * w.y + h.z * w.z + h.w * w.w;
    }
    out[idx] = 1.f / (1.f + expf(-a));
}

// ---------------------------------------------------------------------------
extern "C" void kernel_launch(void* const* d_in, const int* in_sizes, int n_in,
                              void* d_out, int out_size)
{
    const float* pressure = (const float*)d_in[0];
    const float* torque   = (const float*)d_in[1];
    const float* frag     = (const float*)d_in[2];
    const float* pw1 = (const float*)d_in[3];
    const float* pb1 = (const float*)d_in[4];
    const float* pw2 = (const float*)d_in[5];
    const float* pb2 = (const float*)d_in[6];
    const float* tw1 = (const float*)d_in[7];
    const float* tb1 = (const float*)d_in[8];
    const float* tw2 = (const float*)d_in[9];
    const float* tb2 = (const float*)d_in[10];
    const float* fw  = (const float*)d_in[11];
    const float* fb  = (const float*)d_in[12];
    const float* prw = (const float*)d_in[13];
    const float* prb = (const float*)d_in[14];
    const float* Wih = (const float*)d_in[15];
    const float* Whh = (const float*)d_in[16];
    const float* bih = (const float*)d_in[17];
    const float* bhh = (const float*)d_in[18];
    const float* hw  = (const float*)d_in[19];
    const float* hb  = (const float*)d_in[20];
    float* out = (float*)d_out;

    static int smem_set = 0;
    cudaFuncSetAttribute(encode_kernel,
                         cudaFuncAttributeMaxDynamicSharedMemorySize, SMEM_BYTES);
    (void)smem_set;

    encode_kernel<<<ENC_GRID, ENC_THREADS, SMEM_BYTES>>>(
        pressure, torque, frag,
        pw1, pb1, pw2, pb2, tw1, tb1, tw2, tb2,
        fw, fb, prw, prb, Wih, bih, bhh);
    lstm_kernel<<<BB, 256>>>(Whh, out);
    head_kernel<<<(NWIN * 4 + 255) / 256, 256>>>(hw, hb, out);
}

// round 3
// speedup vs baseline: 3.2700x; 1.4209x over previous
#include <cuda_runtime.h>
#include <math.h>

#define BB    64
#define TT    256
#define WW    20
#define NP    6
#define NT    12
#define CH    32
#define LL1   18
#define LL2   16
#define PROJD 64
#define GATES 256
#define NWIN  (BB*TT)   // 16384

#define ENC_GRID    148
#define ENC_THREADS 512
#define ENC_WARPS   (ENC_THREADS/32)

typedef unsigned long long ull;

// Scratch (device globals per allocation rules)
__device__ float g_xg[NWIN * GATES];   // 16 MB: precomputed input gates
__device__ float g_hs[NWIN * PROJD];   // 4 MB : all LSTM hidden states

// ---- packed f32x2 helpers ---------------------------------------------------
__device__ __forceinline__ ull pk2(float lo, float hi) {
    ull r; asm("mov.b64 %0, {%1, %2};" : "=l"(r) : "f"(lo), "f"(hi)); return r;
}
__device__ __forceinline__ float2 unpk(ull a) {
    float2 v; asm("mov.b64 {%0, %1}, %2;" : "=f"(v.x), "=f"(v.y) : "l"(a)); return v;
}
__device__ __forceinline__ void fma2(ull& d, ull a, ull b) {
    asm("fma.rn.f32x2 %0, %1, %2, %0;" : "+l"(d) : "l"(a), "l"(b));
}
__device__ __forceinline__ ull add2(ull a, ull b) {
    ull r; asm("add.rn.f32x2 %0, %1, %2;" : "=l"(r) : "l"(a), "l"(b)); return r;
}

__device__ __forceinline__ float sigf(float x) {
    return __fdividef(1.f, 1.f + __expf(-x));
}
__device__ __forceinline__ float tanh_fast(float x) {
    return 2.f * sigf(2.f * x) - 1.f;
}

// ---- shared memory layout (floats) -----------------------------------------
// conv weights paired over input channels: ull index [(icp*3+t)*32 + lane]
#define S_W1P   0                         // 3 icp *3*32*2  = 576
#define S_W2P   (S_W1P + 576)             // 16*3*32*2      = 3072
#define S_W1T   (S_W2P + 3072)            // 6*3*32*2       = 1152
#define S_W2T   (S_W1T + 1152)            // 3072
#define S_PRWP  (S_W2T + 3072)            // [36 kp][64 j][2] = 4608
#define S_WIHP  (S_PRWP + 4608)           // [32 kp][256 g][2] = 16384
#define S_B1P   (S_WIHP + 16384)
#define S_B2P   (S_B1P + 32)
#define S_B1T   (S_B2P + 32)
#define S_B2T   (S_B1T + 32)
#define S_PRB   (S_B2T + 32)              // 64
#define S_BSUM  (S_PRB + 64)              // 256
#define S_FW    (S_BSUM + 256)            // 8
#define S_FB    (S_FW + 8)                // 8
#define S_WARP  (S_FB + 8)                // per-warp region (mult of 4 floats)

// per-warp buffers (floats): x interleaved [icp][40], h1 interleaved [icp][52]
#define PW_XS    0                        // 6*40 = 240
#define PW_H1    240                      // 16*52 = 832
#define PW_CAT   1072                     // 72
#define PW_FEAT  1144                     // 64
#define PW_SIZE  1216
#define SMEM_FLOATS (S_WARP + ENC_WARPS * PW_SIZE)
#define SMEM_BYTES  (SMEM_FLOATS * 4)

// ---------------------------------------------------------------------------
// Encoder pass with f32x2 pairing over input channels.
// xs2: interleaved pairs [icp][l*2+half]; h12: [icp][p*2+half], row stride 52.
// ---------------------------------------------------------------------------
template<int ICP>
__device__ __forceinline__ void encode_f2(
    const float* __restrict__ xs2,
    const ull* __restrict__ w1p, const float* __restrict__ b1s,
    const ull* __restrict__ w2p, const float* __restrict__ b2s,
    float* __restrict__ h12,
    float* __restrict__ outp, int lane)
{
    // conv1 -> relu -> h12
    {
        ull acc[LL1];
        ull binit = pk2(b1s[lane], 0.f);
        #pragma unroll
        for (int p = 0; p < LL1; p++) acc[p] = binit;
        #pragma unroll 1
        for (int icp = 0; icp < ICP; icp++) {
            ull xv[WW];
            const ulonglong2* xp = (const ulonglong2*)(xs2 + icp * 40);
            #pragma unroll
            for (int q = 0; q < 10; q++) { ulonglong2 t = xp[q]; xv[2*q] = t.x; xv[2*q+1] = t.y; }
            const ull* wb_ = w1p + icp * 96;
            ull w0 = wb_[lane], w1 = wb_[32 + lane], w2 = wb_[64 + lane];
            #pragma unroll
            for (int p = 0; p < LL1; p++) {
                fma2(acc[p], xv[p],     w0);
                fma2(acc[p], xv[p + 1], w1);
                fma2(acc[p], xv[p + 2], w2);
            }
        }
        float* dst = h12 + (lane >> 1) * 52 + (lane & 1);
        #pragma unroll
        for (int p = 0; p < LL1; p++) {
            float2 r = unpk(acc[p]);
            dst[2 * p] = fmaxf(r.x + r.y, 0.f);
        }
    }
    __syncwarp();

    // conv2 -> relu -> mean
    {
        ull acc[LL2];
        ull binit = pk2(b2s[lane], 0.f);
        #pragma unroll
        for (int p = 0; p < LL2; p++) acc[p] = binit;
        #pragma unroll 1
        for (int icp = 0; icp < 16; icp++) {
            ull hv[LL1];
            const ulonglong2* hp = (const ulonglong2*)(h12 + icp * 52);
            #pragma unroll
            for (int q = 0; q < 9; q++) { ulonglong2 t = hp[q]; hv[2*q] = t.x; hv[2*q+1] = t.y; }
            const ull* wb_ = w2p + icp * 96;
            ull w0 = wb_[lane], w1 = wb_[32 + lane], w2 = wb_[64 + lane];
            #pragma unroll
            for (int p = 0; p < LL2; p++) {
                fma2(acc[p], hv[p],     w0);
                fma2(acc[p], hv[p + 1], w1);
                fma2(acc[p], hv[p + 2], w2);
            }
        }
        float sum = 0.f;
        #pragma unroll
        for (int p = 0; p < LL2; p++) {
            float2 r = unpk(acc[p]);
            sum += fmaxf(r.x + r.y, 0.f);
        }
        outp[lane] = sum * (1.f / 16.f);
    }
    __syncwarp();
}

// ---------------------------------------------------------------------------
__global__ __launch_bounds__(ENC_THREADS, 1) void encode_kernel(
    const float* __restrict__ pressure, const float* __restrict__ torque,
    const float* __restrict__ frag,
    const float* __restrict__ pw1, const float* __restrict__ pb1,
    const float* __restrict__ pw2, const float* __restrict__ pb2,
    const float* __restrict__ tw1, const float* __restrict__ tb1,
    const float* __restrict__ tw2, const float* __restrict__ tb2,
    const float* __restrict__ fw,  const float* __restrict__ fb,
    const float* __restrict__ prw, const float* __restrict__ prb,
    const float* __restrict__ Wih, const float* __restrict__ bih,
    const float* __restrict__ bhh)
{
    extern __shared__ __align__(16) float sm[];
    const int tid = threadIdx.x;
    const int warp = tid >> 5, lane = tid & 31;

    // ---- stage paired weights into smem ----
    for (int i = tid; i < 576; i += ENC_THREADS) {
        int half = i & 1, j = i >> 1, ln = j & 31, q = j >> 5;
        int t = q % 3, icp = q / 3, ic = 2 * icp + half;
        sm[S_W1P + i] = pw1[ln * (NP * 3) + ic * 3 + t];
    }
    for (int i = tid; i < 3072; i += ENC_THREADS) {
        int half = i & 1, j = i >> 1, ln = j & 31, q = j >> 5;
        int t = q % 3, icp = q / 3, ic = 2 * icp + half;
        sm[S_W2P + i] = pw2[ln * (CH * 3) + ic * 3 + t];
    }
    for (int i = tid; i < 1152; i += ENC_THREADS) {
        int half = i & 1, j = i >> 1, ln = j & 31, q = j >> 5;
        int t = q % 3, icp = q / 3, ic = 2 * icp + half;
        sm[S_W1T + i] = tw1[ln * (NT * 3) + ic * 3 + t];
    }
    for (int i = tid; i < 3072; i += ENC_THREADS) {
        int half = i & 1, j = i >> 1, ln = j & 31, q = j >> 5;
        int t = q % 3, icp = q / 3, ic = 2 * icp + half;
        sm[S_W2T + i] = tw2[ln * (CH * 3) + ic * 3 + t];
    }
    for (int i = tid; i < 4608; i += ENC_THREADS) {
        int half = i & 1, j = i >> 1, jc = j & 63, kp = j >> 6;
        sm[S_PRWP + i] = prw[jc * 72 + 2 * kp + half];
    }
    for (int i = tid; i < 16384; i += ENC_THREADS) {
        int half = i & 1, j = i >> 1, g = j & 255, kp = j >> 8;
        sm[S_WIHP + i] = Wih[g * 64 + 2 * kp + half];
    }
    if (tid < 32) {
        sm[S_B1P + tid] = pb1[tid];
        sm[S_B2P + tid] = pb2[tid];
        sm[S_B1T + tid] = tb1[tid];
        sm[S_B2T + tid] = tb2[tid];
    }
    if (tid < 64) sm[S_PRB + tid] = prb[tid];
    if (tid < GATES) sm[S_BSUM + tid] = bih[tid] + bhh[tid];
    if (tid < 8) { sm[S_FW + tid] = fw[tid]; sm[S_FB + tid] = fb[tid]; }
    __syncthreads();

    float* wb    = sm + S_WARP + warp * PW_SIZE;
    float* xs2   = wb + PW_XS;
    float* h12   = wb + PW_H1;
    float* cats  = wb + PW_CAT;
    float* feats = wb + PW_FEAT;

    // hoisted staging index tables (lane constants)
    int dp[4], dt[8];
    #pragma unroll
    for (int k = 0; k < 4; k++) {
        int i = lane + 32 * k;
        if (i < WW * NP) { int l = i / NP, c = i % NP; dp[k] = (c >> 1) * 40 + 2 * l + (c & 1); }
        else dp[k] = -1;
    }
    #pragma unroll
    for (int k = 0; k < 8; k++) {
        int i = lane + 32 * k;
        if (i < WW * NT) { int l = i / NT, c = i % NT; dt[k] = (c >> 1) * 40 + 2 * l + (c & 1); }
        else dt[k] = -1;
    }

    const ull* w1pp = (const ull*)(sm + S_W1P);
    const ull* w2pp = (const ull*)(sm + S_W2P);
    const ull* w1tp = (const ull*)(sm + S_W1T);
    const ull* w2tp = (const ull*)(sm + S_W2T);

    const int gwarp = blockIdx.x * ENC_WARPS + warp;

    for (int n = gwarp; n < NWIN; n += ENC_GRID * ENC_WARPS) {
        const int b = n / TT;

        // pressure window -> interleaved xs2
        {
            const float* src = pressure + (size_t)n * (WW * NP);
            #pragma unroll
            for (int k = 0; k < 4; k++)
                if (dp[k] >= 0) xs2[dp[k]] = src[lane + 32 * k];
        }
        __syncwarp();
        encode_f2<NP/2>(xs2, w1pp, sm + S_B1P, w2pp, sm + S_B2P, h12, cats, lane);

        // torque window
        {
            const float* src = torque + (size_t)n * (WW * NT);
            #pragma unroll
            for (int k = 0; k < 8; k++)
                if (dt[k] >= 0) xs2[dt[k]] = src[lane + 32 * k];
        }
        __syncwarp();
        encode_f2<NT/2>(xs2, w1tp, sm + S_B1T, w2tp, sm + S_B2T, h12, cats + CH, lane);

        // fragility features
        if (lane < 8) {
            float fv = __ldg(frag + b);
            cats[2 * CH + lane] = fmaxf(fv * sm[S_FW + lane] + sm[S_FB + lane], 0.f);
        }
        __syncwarp();

        // projection 72 -> 64 (relu), k-paired f32x2
        {
            ull a0 = pk2(sm[S_PRB + lane], 0.f);
            ull a1 = pk2(sm[S_PRB + lane + 32], 0.f);
            const ull* cp = (const ull*)cats;
            const ull* pp = (const ull*)(sm + S_PRWP);
            #pragma unroll 6
            for (int kp = 0; kp < 36; kp++) {
                ull cv = cp[kp];
                fma2(a0, cv, pp[kp * 64 + lane]);
                fma2(a1, cv, pp[kp * 64 + lane + 32]);
            }
            float2 r0 = unpk(a0), r1 = unpk(a1);
            feats[lane]      = fmaxf(r0.x + r0.y, 0.f);
            feats[lane + 32] = fmaxf(r1.x + r1.y, 0.f);
        }
        __syncwarp();

        // xg = feat @ Wih^T + (bih+bhh), k-paired f32x2, 8 gates per lane
        {
            ull acc[8];
            #pragma unroll
            for (int u = 0; u < 8; u++) acc[u] = pk2(sm[S_BSUM + lane + 32 * u], 0.f);
            const ull* fp = (const ull*)feats;
            const ull* wp = (const ull*)(sm + S_WIHP);
            #pragma unroll 4
            for (int kp = 0; kp < 32; kp++) {
                ull fv = fp[kp];
                #pragma unroll
                for (int u = 0; u < 8; u++)
                    fma2(acc[u], fv, wp[kp * 256 + lane + 32 * u]);
            }
            float* xgo = g_xg + (size_t)n * GATES;
            #pragma unroll
            for (int u = 0; u < 8; u++) {
                float2 r = unpk(acc[u]);
                xgo[lane + 32 * u] = r.x + r.y;
            }
        }
        __syncwarp();
    }
}

// ---------------------------------------------------------------------------
// LSTM: one block per batch row, thread = gate (0..255), f32x2 dot products.
// ---------------------------------------------------------------------------
__global__ __launch_bounds__(256) void lstm_kernel(
    const float* __restrict__ Whh, float* __restrict__ out_tail)
{
    const int b = blockIdx.x;
    const int g = threadIdx.x;

    __shared__ __align__(16) float h_s[PROJD];
    __shared__ float g_sh[GATES];

    ull whh2[32];
    const ulonglong2* wr = (const ulonglong2*)(Whh + g * PROJD);
    #pragma unroll
    for (int k = 0; k < 16; k++) {
        ulonglong2 t = wr[k];
        whh2[2 * k] = t.x; whh2[2 * k + 1] = t.y;
    }
    if (g < PROJD) h_s[g] = 0.f;
    float c = 0.f;
    __syncthreads();

    const float* xgb = g_xg + (size_t)b * TT * GATES + g;
    float xnext = xgb[0];
    float* hso = g_hs + (size_t)b * TT * PROJD;

    for (int t = 0; t < TT; t++) {
        ull a0 = pk2(xnext, 0.f), a1 = pk2(0.f, 0.f);
        ull a2 = pk2(0.f, 0.f),  a3 = pk2(0.f, 0.f);
        if (t + 1 < TT) xnext = xgb[(t + 1) * GATES];   // prefetch next step
        const ulonglong2* hp = (const ulonglong2*)h_s;
        #pragma unroll
        for (int k = 0; k < 8; k++) {
            ulonglong2 h01 = hp[2 * k], h23 = hp[2 * k + 1];
            fma2(a0, h01.x, whh2[4 * k]);
            fma2(a1, h01.y, whh2[4 * k + 1]);
            fma2(a2, h23.x, whh2[4 * k + 2]);
            fma2(a3, h23.y, whh2[4 * k + 3]);
        }
        float2 r = unpk(add2(add2(a0, a1), add2(a2, a3)));
        g_sh[g] = r.x + r.y;
        __syncthreads();
        if (g < PROJD) {
            float iv = g_sh[g], fv = g_sh[g + 64], gg = g_sh[g + 128], ov = g_sh[g + 192];
            c = sigf(fv) * c + sigf(iv) * tanh_fast(gg);
            float hn = sigf(ov) * tanh_fast(c);
            h_s[g] = hn;
            hso[t * PROJD + g] = hn;
        }
        __syncthreads();
    }
    if (g < PROJD) {
        out_tail[NWIN * 4 + b * PROJD + g] = h_s[g];                 // hT
        out_tail[NWIN * 4 + BB * PROJD + b * PROJD + g] = c;         // cT
    }
}

// ---------------------------------------------------------------------------
// Head: out[n,k] = sigmoid(h[n] . hw[k] + hb[k])
// ---------------------------------------------------------------------------
__global__ __launch_bounds__(256) void head_kernel(
    const float* __restrict__ hw, const float* __restrict__ hb,
    float* __restrict__ out)
{
    int idx = blockIdx.x * blockDim.x + threadIdx.x;
    if (idx >= NWIN * 4) return;
    int k = idx & 3;
    int n = idx >> 2;
    const ulonglong2* hp = (const ulonglong2*)(g_hs + (size_t)n * PROJD);
    const ulonglong2* wp = (const ulonglong2*)(hw + k * PROJD);
    ull a0 = pk2(__ldg(hb + k), 0.f), a1 = pk2(0.f, 0.f);
    #pragma unroll
    for (int q = 0; q < 16; q++) {
        ulonglong2 h = hp[q];
        ulonglong2 w = wp[q];
        fma2(a0, h.x, w.x);
        fma2(a1, h.y, w.y);
    }
    float2 r = unpk(add2(a0, a1));
    out[idx] = sigf(r.x + r.y);
}

// ---------------------------------------------------------------------------
extern "C" void kernel_launch(void* const* d_in, const int* in_sizes, int n_in,
                              void* d_out, int out_size)
{
    const float* pressure = (const float*)d_in[0];
    const float* torque   = (const float*)d_in[1];
    const float* frag     = (const float*)d_in[2];
    const float* pw1 = (const float*)d_in[3];
    const float* pb1 = (const float*)d_in[4];
    const float* pw2 = (const float*)d_in[5];
    const float* pb2 = (const float*)d_in[6];
    const float* tw1 = (const float*)d_in[7];
    const float* tb1 = (const float*)d_in[8];
    const float* tw2 = (const float*)d_in[9];
    const float* tb2 = (const float*)d_in[10];
    const float* fw  = (const float*)d_in[11];
    const float* fb  = (const float*)d_in[12];
    const float* prw = (const float*)d_in[13];
    const float* prb = (const float*)d_in[14];
    const float* Wih = (const float*)d_in[15];
    const float* Whh = (const float*)d_in[16];
    const float* bih = (const float*)d_in[17];
    const float* bhh = (const float*)d_in[18];
    const float* hw  = (const float*)d_in[19];
    const float* hb  = (const float*)d_in[20];
    float* out = (float*)d_out;

    cudaFuncSetAttribute(encode_kernel,
                         cudaFuncAttributeMaxDynamicSharedMemorySize, SMEM_BYTES);

    encode_kernel<<<ENC_GRID, ENC_THREADS, SMEM_BYTES>>>(
        pressure, torque, frag,
        pw1, pb1, pw2, pb2, tw1, tb1, tw2, tb2,
        fw, fb, prw, prb, Wih, bih, bhh);
    lstm_kernel<<<BB, 256>>>(Whh, out);
    head_kernel<<<(NWIN * 4 + 255) / 256, 256>>>(hw, hb, out);
}